// round 1
// baseline (speedup 1.0000x reference)
#include <cuda_runtime.h>
#include <cuda_bf16.h>
#include <cstdint>

#define NE   262144
#define NW   1048576
#define DD   128
#define NRBF 6
#define ADIM 49
#define NBIL 8

// ---------------- scratch (static device globals; no allocs) ----------------
__device__ float g_ME[(size_t)NE * DD];   // silu(m_ji@nbr_m_w+b) * (e_rbf@e_rbf_w)
__device__ float g_TR[(size_t)NE * DD];   // transf_m_ji
__device__ float g_S [(size_t)NE * NBIL]; // segment-summed t_a
__device__ float g_X [(size_t)NE * DD];   // running activation
__device__ float g_H [(size_t)NE * DD];   // hidden of residual blocks

__device__ __forceinline__ float silu_f(float x) {
    return x / (1.f + __expf(-x));
}

// ============================================================================
// K1: per-edge precompute.  TB=64 edges/CTA, 256 threads.
//   ME[e]  = silu(m_ji[e]@nbr_m_w + nbr_m_b) * (e_rbf[e]@e_rbf_w)
//   TR[e]  = silu(m_ji[e]@m_ji_w + m_ji_b)
// Also zeroes g_S for this block's edge range.
// ============================================================================
#define K1_TB 64
#define K1_XPAD 68   // row stride for transposed x tile (floats)

__global__ __launch_bounds__(256, 1)
void k_edge_pre(const float* __restrict__ m_ji, const float* __restrict__ e_rbf,
                const float* __restrict__ nbr_m_w, const float* __restrict__ nbr_m_b,
                const float* __restrict__ e_rbf_w, const float* __restrict__ m_ji_w,
                const float* __restrict__ m_ji_b)
{
    extern __shared__ float sm[];
    float* xsT  = sm;                    // [128][K1_XPAD]  (x transposed: xsT[d][e])
    float* ws   = xsT + DD * K1_XPAD;    // [128][128]      staged weight
    float* erbf = ws + DD * DD;          // [64][6]
    float* erw  = erbf + K1_TB * NRBF;   // [6][128]
    float* b1s  = erw + NRBF * DD;       // [128]
    float* b2s  = b1s + DD;              // [128]

    const int tid   = threadIdx.x;
    const int e0blk = blockIdx.x * K1_TB;

    // zero the S region for these edges (runs before triplet kernel)
    for (int i = tid; i < K1_TB * NBIL; i += 256) g_S[(size_t)e0blk * NBIL + i] = 0.f;

    // stage x tile transposed
    for (int i = tid; i < K1_TB * DD; i += 256) {
        int e = i >> 7, d = i & 127;
        xsT[d * K1_XPAD + e] = m_ji[(size_t)(e0blk + e) * DD + d];
    }
    for (int i = tid; i < K1_TB * NRBF; i += 256) erbf[i] = e_rbf[(size_t)e0blk * NRBF + i];
    for (int i = tid; i < NRBF * DD; i += 256) erw[i] = e_rbf_w[i];
    for (int i = tid; i < DD; i += 256) { b1s[i] = nbr_m_b[i]; b2s[i] = m_ji_b[i]; }
    for (int i = tid; i < DD * DD; i += 256) ws[i] = nbr_m_w[i];
    __syncthreads();

    const int tc = tid & 15, te = tid >> 4;
    const int c0 = tc * 8, eo = te * 4;

    float acc[4][8];
#pragma unroll
    for (int e = 0; e < 4; e++)
#pragma unroll
        for (int c = 0; c < 8; c++) acc[e][c] = 0.f;

#pragma unroll 4
    for (int k = 0; k < DD; k++) {
        const float4 a4 = *(const float4*)&xsT[k * K1_XPAD + eo];
        const float4 bA = *(const float4*)&ws[k * DD + c0];
        const float4 bB = *(const float4*)&ws[k * DD + c0 + 4];
        const float av[4] = {a4.x, a4.y, a4.z, a4.w};
        const float bv[8] = {bA.x, bA.y, bA.z, bA.w, bB.x, bB.y, bB.z, bB.w};
#pragma unroll
        for (int e = 0; e < 4; e++)
#pragma unroll
            for (int c = 0; c < 8; c++) acc[e][c] = fmaf(av[e], bv[c], acc[e][c]);
    }

    // epilogue 1: ME = silu(acc+b1) * (e_rbf @ e_rbf_w)
#pragma unroll
    for (int e = 0; e < 4; e++) {
        const int ee = eo + e;
        float ein[NRBF];
#pragma unroll
        for (int r = 0; r < NRBF; r++) ein[r] = erbf[ee * NRBF + r];
        float out[8];
#pragma unroll
        for (int c = 0; c < 8; c++) {
            const int cc = c0 + c;
            float t = silu_f(acc[e][c] + b1s[cc]);
            float er = 0.f;
#pragma unroll
            for (int r = 0; r < NRBF; r++) er = fmaf(ein[r], erw[r * DD + cc], er);
            out[c] = t * er;
        }
        size_t base = (size_t)(e0blk + ee) * DD + c0;
        *(float4*)&g_ME[base]     = make_float4(out[0], out[1], out[2], out[3]);
        *(float4*)&g_ME[base + 4] = make_float4(out[4], out[5], out[6], out[7]);
    }
    __syncthreads();

    // restage ws = m_ji_w, redo GEMM for transf
    for (int i = tid; i < DD * DD; i += 256) ws[i] = m_ji_w[i];
    __syncthreads();

#pragma unroll
    for (int e = 0; e < 4; e++)
#pragma unroll
        for (int c = 0; c < 8; c++) acc[e][c] = 0.f;

#pragma unroll 4
    for (int k = 0; k < DD; k++) {
        const float4 a4 = *(const float4*)&xsT[k * K1_XPAD + eo];
        const float4 bA = *(const float4*)&ws[k * DD + c0];
        const float4 bB = *(const float4*)&ws[k * DD + c0 + 4];
        const float av[4] = {a4.x, a4.y, a4.z, a4.w};
        const float bv[8] = {bA.x, bA.y, bA.z, bA.w, bB.x, bB.y, bB.z, bB.w};
#pragma unroll
        for (int e = 0; e < 4; e++)
#pragma unroll
            for (int c = 0; c < 8; c++) acc[e][c] = fmaf(av[e], bv[c], acc[e][c]);
    }

#pragma unroll
    for (int e = 0; e < 4; e++) {
        const int ee = eo + e;
        float out[8];
#pragma unroll
        for (int c = 0; c < 8; c++) out[c] = silu_f(acc[e][c] + b2s[c0 + c]);
        size_t base = (size_t)(e0blk + ee) * DD + c0;
        *(float4*)&g_TR[base]     = make_float4(out[0], out[1], out[2], out[3]);
        *(float4*)&g_TR[base + 4] = make_float4(out[4], out[5], out[6], out[7]);
    }
}

// ============================================================================
// K2: triplet pass.  t_a = a_sbf @ a_sbf_w ([W,8]), atomically segment-summed
// into g_S[kj].  128 triplets per 128-thread CTA.
// ============================================================================
#define K2_TW 128
__global__ __launch_bounds__(128, 8)
void k_triplet(const float* __restrict__ a_sbf, const float* __restrict__ a_sbf_w,
               const int* __restrict__ kj_idx)
{
    __shared__ float as[K2_TW * ADIM];
    __shared__ float aw[ADIM * NBIL];
    const int tid = threadIdx.x;
    const size_t w0 = (size_t)blockIdx.x * K2_TW;

    for (int i = tid; i < K2_TW * ADIM; i += 128) as[i] = a_sbf[w0 * ADIM + i];
    for (int i = tid; i < ADIM * NBIL; i += 128) aw[i] = a_sbf_w[i];
    __syncthreads();

    const float* row = &as[tid * ADIM];
    float ta[NBIL];
#pragma unroll
    for (int j = 0; j < NBIL; j++) ta[j] = 0.f;
    for (int k = 0; k < ADIM; k++) {
        const float a = row[k];
#pragma unroll
        for (int j = 0; j < NBIL; j++) ta[j] = fmaf(a, aw[k * NBIL + j], ta[j]);
    }
    const int kj = kj_idx[w0 + tid];
    float* dst = &g_S[(size_t)kj * NBIL];
#pragma unroll
    for (int j = 0; j < NBIL; j++) atomicAdd(&dst[j], ta[j]);
}

// ============================================================================
// K3: directed = (S ⊗ ME) @ final_w^T  + transf   -> g_X
// GEMM [E,1024]@[1024,128]; A[e, j*128+l] = S[e,j]*ME[e,l] generated on the fly.
// 128 edges/CTA, 256 threads, 8x8 per thread.
// ============================================================================
#define PAD 132
__global__ __launch_bounds__(256, 1)
void k_einsum(const float* __restrict__ final_w)
{
    extern __shared__ float sm[];
    float* MEt = sm;               // [128 l][PAD] -> MEt[l][e]
    float* bsm = MEt + DD * PAD;   // [128 l][PAD] -> bsm[l][i] = final_w[i][j][l]
    float* Ssm = bsm + DD * PAD;   // [128 e][8]

    const int tid   = threadIdx.x;
    const int e0blk = blockIdx.x * 128;

    for (int i = tid; i < 128 * DD; i += 256) {
        int e = i >> 7, l = i & 127;
        MEt[l * PAD + e] = g_ME[(size_t)(e0blk + e) * DD + l];
    }
    for (int i = tid; i < 128 * NBIL; i += 256) Ssm[i] = g_S[(size_t)e0blk * NBIL + i];

    const int tc = tid & 15, te = tid >> 4;
    const int c0 = tc * 8, eo = te * 8;

    float acc[8][8];
#pragma unroll
    for (int e = 0; e < 8; e++)
#pragma unroll
        for (int c = 0; c < 8; c++) acc[e][c] = 0.f;

    for (int j = 0; j < NBIL; j++) {
        __syncthreads();
        for (int n = tid; n < DD * DD; n += 256) {
            int i = n >> 7, l = n & 127;
            bsm[l * PAD + i] = final_w[(size_t)i * (NBIL * DD) + j * DD + l];
        }
        __syncthreads();

        float s[8];
#pragma unroll
        for (int e = 0; e < 8; e++) s[e] = Ssm[(eo + e) * NBIL + j];

#pragma unroll 2
        for (int l = 0; l < DD; l++) {
            const float4 m0 = *(const float4*)&MEt[l * PAD + eo];
            const float4 m1 = *(const float4*)&MEt[l * PAD + eo + 4];
            const float4 bA = *(const float4*)&bsm[l * PAD + c0];
            const float4 bB = *(const float4*)&bsm[l * PAD + c0 + 4];
            const float av[8] = {m0.x * s[0], m0.y * s[1], m0.z * s[2], m0.w * s[3],
                                 m1.x * s[4], m1.y * s[5], m1.z * s[6], m1.w * s[7]};
            const float bv[8] = {bA.x, bA.y, bA.z, bA.w, bB.x, bB.y, bB.z, bB.w};
#pragma unroll
            for (int e = 0; e < 8; e++)
#pragma unroll
                for (int c = 0; c < 8; c++) acc[e][c] = fmaf(av[e], bv[c], acc[e][c]);
        }
    }

    // epilogue: + transf, write X0
#pragma unroll
    for (int e = 0; e < 8; e++) {
        const size_t base = (size_t)(e0blk + eo + e) * DD + c0;
        float4 t0 = *(const float4*)&g_TR[base];
        float4 t1 = *(const float4*)&g_TR[base + 4];
        float4 o0 = make_float4(acc[e][0] + t0.x, acc[e][1] + t0.y,
                                acc[e][2] + t0.z, acc[e][3] + t0.w);
        float4 o1 = make_float4(acc[e][4] + t1.x, acc[e][5] + t1.y,
                                acc[e][6] + t1.z, acc[e][7] + t1.w);
        *(float4*)&g_X[base]     = o0;
        *(float4*)&g_X[base + 4] = o1;
    }
}

// ============================================================================
// K4: generic dense row layer: Y = silu(X@W + b) [+ skip]
// 128 edges/CTA, 256 threads, 8x8 per thread.
// ============================================================================
__global__ __launch_bounds__(256, 1)
void k_layer(const float* __restrict__ X, const float* __restrict__ W,
             const float* __restrict__ b, const float* __restrict__ skip,
             float* __restrict__ Y)
{
    extern __shared__ float sm[];
    float* Xt   = sm;              // [128 k][PAD] -> Xt[k][e]
    float* wsm  = Xt + DD * PAD;   // [128 k][PAD] -> wsm[k][i]
    float* bias = wsm + DD * PAD;  // [128]

    const int tid   = threadIdx.x;
    const int e0blk = blockIdx.x * 128;

    for (int i = tid; i < 128 * DD; i += 256) {
        int e = i >> 7, d = i & 127;
        Xt[d * PAD + e] = X[(size_t)(e0blk + e) * DD + d];
    }
    for (int i = tid; i < DD * DD; i += 256) {
        int k = i >> 7, c = i & 127;
        wsm[k * PAD + c] = W[i];
    }
    for (int i = tid; i < DD; i += 256) bias[i] = b[i];
    __syncthreads();

    const int tc = tid & 15, te = tid >> 4;
    const int c0 = tc * 8, eo = te * 8;

    float acc[8][8];
#pragma unroll
    for (int e = 0; e < 8; e++)
#pragma unroll
        for (int c = 0; c < 8; c++) acc[e][c] = 0.f;

#pragma unroll 2
    for (int k = 0; k < DD; k++) {
        const float4 a0 = *(const float4*)&Xt[k * PAD + eo];
        const float4 a1 = *(const float4*)&Xt[k * PAD + eo + 4];
        const float4 bA = *(const float4*)&wsm[k * PAD + c0];
        const float4 bB = *(const float4*)&wsm[k * PAD + c0 + 4];
        const float av[8] = {a0.x, a0.y, a0.z, a0.w, a1.x, a1.y, a1.z, a1.w};
        const float bv[8] = {bA.x, bA.y, bA.z, bA.w, bB.x, bB.y, bB.z, bB.w};
#pragma unroll
        for (int e = 0; e < 8; e++)
#pragma unroll
            for (int c = 0; c < 8; c++) acc[e][c] = fmaf(av[e], bv[c], acc[e][c]);
    }

#pragma unroll
    for (int e = 0; e < 8; e++) {
        const size_t base = (size_t)(e0blk + eo + e) * DD + c0;
        float v[8];
#pragma unroll
        for (int c = 0; c < 8; c++) v[c] = silu_f(acc[e][c] + bias[c0 + c]);
        if (skip) {
            float4 s0 = *(const float4*)&skip[base];
            float4 s1 = *(const float4*)&skip[base + 4];
            v[0] += s0.x; v[1] += s0.y; v[2] += s0.z; v[3] += s0.w;
            v[4] += s1.x; v[5] += s1.y; v[6] += s1.z; v[7] += s1.w;
        }
        *(float4*)&Y[base]     = make_float4(v[0], v[1], v[2], v[3]);
        *(float4*)&Y[base + 4] = make_float4(v[4], v[5], v[6], v[7]);
    }
}

// ============================================================================
// host launcher
// ============================================================================
extern "C" void kernel_launch(void* const* d_in, const int* in_sizes, int n_in,
                              void* d_out, int out_size)
{
    const float* m_ji    = (const float*)d_in[0];
    const float* e_rbf   = (const float*)d_in[1];
    const float* a_sbf   = (const float*)d_in[2];
    // d_in[3] nbr_list, d_in[4] angle_list: unused by reference
    const int*   kj_idx  = (const int*)d_in[5];
    const float* nbr_m_w = (const float*)d_in[6];
    const float* nbr_m_b = (const float*)d_in[7];
    const float* e_rbf_w = (const float*)d_in[8];
    const float* a_sbf_w = (const float*)d_in[9];
    const float* final_w = (const float*)d_in[10];
    const float* m_ji_w  = (const float*)d_in[11];
    const float* m_ji_b  = (const float*)d_in[12];
    const float* post_w  = (const float*)d_in[13];
    const float* post_b  = (const float*)d_in[14];
    const float* res_w   = (const float*)d_in[15];
    const float* res_b   = (const float*)d_in[16];
    float* out = (float*)d_out;

    float *pX, *pH, *pTR;
    cudaGetSymbolAddress((void**)&pX,  g_X);
    cudaGetSymbolAddress((void**)&pH,  g_H);
    cudaGetSymbolAddress((void**)&pTR, g_TR);

    const int SMEM1 = (DD * K1_XPAD + DD * DD + K1_TB * NRBF + NRBF * DD + 2 * DD) * 4;
    const int SMEM3 = (DD * PAD * 2 + 128 * NBIL) * 4;
    const int SMEM4 = (DD * PAD * 2 + DD) * 4;
    cudaFuncSetAttribute(k_edge_pre, cudaFuncAttributeMaxDynamicSharedMemorySize, SMEM1);
    cudaFuncSetAttribute(k_einsum,   cudaFuncAttributeMaxDynamicSharedMemorySize, SMEM3);
    cudaFuncSetAttribute(k_layer,    cudaFuncAttributeMaxDynamicSharedMemorySize, SMEM4);

    // 1) per-edge precompute (also zeroes g_S)
    k_edge_pre<<<NE / K1_TB, 256, SMEM1>>>(m_ji, e_rbf, nbr_m_w, nbr_m_b,
                                           e_rbf_w, m_ji_w, m_ji_b);
    // 2) triplet t_a + segment sum into g_S
    k_triplet<<<NW / K2_TW, 128>>>(a_sbf, a_sbf_w, kj_idx);
    // 3) directed + transf -> g_X
    k_einsum<<<NE / 128, 256, SMEM3>>>(final_w);

    // 4) tail chain
    const int WD = DD * DD;
    // res block 0
    k_layer<<<NE / 128, 256, SMEM4>>>(pX, res_w + 0 * WD, res_b + 0 * DD, nullptr, pH);
    k_layer<<<NE / 128, 256, SMEM4>>>(pH, res_w + 1 * WD, res_b + 1 * DD, pX, pX);
    // post + transf skip
    k_layer<<<NE / 128, 256, SMEM4>>>(pX, post_w, post_b, pTR, pX);
    // res block 1
    k_layer<<<NE / 128, 256, SMEM4>>>(pX, res_w + 2 * WD, res_b + 2 * DD, nullptr, pH);
    k_layer<<<NE / 128, 256, SMEM4>>>(pH, res_w + 3 * WD, res_b + 3 * DD, pX, pX);
    // res block 2
    k_layer<<<NE / 128, 256, SMEM4>>>(pX, res_w + 4 * WD, res_b + 4 * DD, nullptr, pH);
    k_layer<<<NE / 128, 256, SMEM4>>>(pH, res_w + 5 * WD, res_b + 5 * DD, pX, out);
}

// round 2
// speedup vs baseline: 1.1115x; 1.1115x over previous
#include <cuda_runtime.h>
#include <cuda_bf16.h>
#include <cstdint>

#define NE   262144
#define NW   1048576
#define DD   128
#define NRBF 6
#define ADIM 49
#define NBIL 8

typedef unsigned long long ull;

// ---------------- scratch (static device globals; no allocs) ----------------
__device__ float g_ME[(size_t)NE * DD];   // silu(m_ji@nbr_m_w+b) * (e_rbf@e_rbf_w)
__device__ float g_TR[(size_t)NE * DD];   // transf_m_ji
__device__ float g_S [(size_t)NE * NBIL]; // segment-summed t_a
__device__ float g_X [(size_t)NE * DD];   // running activation
__device__ float g_H [(size_t)NE * DD];   // hidden of residual blocks

__device__ __forceinline__ float silu_f(float x) {
    return x / (1.f + __expf(-x));
}

__device__ __forceinline__ ull pk2(float lo, float hi) {
    ull r; asm("mov.b64 %0, {%1, %2};" : "=l"(r) : "f"(lo), "f"(hi)); return r;
}
__device__ __forceinline__ void fma2(ull& d, ull a, ull b) {
    asm("fma.rn.f32x2 %0, %1, %2, %0;" : "+l"(d) : "l"(a), "l"(b));
}
__device__ __forceinline__ float2 up2(ull v) {
    float2 f; asm("mov.b64 {%0, %1}, %2;" : "=f"(f.x), "=f"(f.y) : "l"(v)); return f;
}

// tile geometry shared by the big kernels:
//  128 edges / CTA, 256 threads, output columns in 4 passes of 32.
//  thread: tc = tid&15 -> 2 columns (2*tc, 2*tc+1); te = tid>>4 -> 8 edges.
//  A tile transposed in smem [k][132]; W duplicated [k][68] (32 cols as (w,w) pairs).
#define PX 132
#define PW 68

// ============================================================================
// K1: per-edge precompute (ME and TR), 128 edges/CTA.
// ============================================================================
__global__ __launch_bounds__(256, 2)
void k_edge_pre(const float* __restrict__ m_ji, const float* __restrict__ e_rbf,
                const float* __restrict__ nbr_m_w, const float* __restrict__ nbr_m_b,
                const float* __restrict__ e_rbf_w, const float* __restrict__ m_ji_w,
                const float* __restrict__ m_ji_b)
{
    extern __shared__ float sm[];
    float* Xt   = sm;                 // [128][PX]
    float* wdup = Xt + DD * PX;       // [128][PW]
    float* erbf = wdup + DD * PW;     // [128][6]
    float* erw  = erbf + DD * NRBF;   // [6][128]
    float* b1s  = erw + NRBF * DD;    // [128]
    float* b2s  = b1s + DD;           // [128]

    const int tid = threadIdx.x;
    const int e0  = blockIdx.x * 128;

    for (int i = tid; i < 128 * NBIL; i += 256) g_S[(size_t)e0 * NBIL + i] = 0.f;

    for (int i = tid; i < 128 * DD; i += 256) {
        int e = i >> 7, d = i & 127;
        Xt[d * PX + e] = m_ji[(size_t)(e0 + e) * DD + d];
    }
    for (int i = tid; i < 128 * NRBF; i += 256) erbf[i] = e_rbf[(size_t)e0 * NRBF + i];
    for (int i = tid; i < NRBF * DD; i += 256) erw[i] = e_rbf_w[i];
    if (tid < DD) { b1s[tid] = nbr_m_b[tid]; b2s[tid] = m_ji_b[tid]; }

    const int tc = tid & 15, te = tid >> 4;
    const int cw = tc * 4;     // word offset into wdup row
    const int eo = te * 8;

    for (int pass = 0; pass < 2; pass++) {
        const float* W = pass ? m_ji_w : nbr_m_w;
        for (int h = 0; h < 4; h++) {
            __syncthreads();
            for (int i = tid; i < 128 * 32; i += 256) {
                int k = i >> 5, c = i & 31;
                float v = W[k * DD + h * 32 + c];
                wdup[k * PW + 2 * c]     = v;
                wdup[k * PW + 2 * c + 1] = v;
            }
            __syncthreads();

            ull acc[4][2];
#pragma unroll
            for (int p = 0; p < 4; p++) { acc[p][0] = 0ull; acc[p][1] = 0ull; }

#pragma unroll 4
            for (int k = 0; k < DD; k++) {
                const float4 a0 = *(const float4*)&Xt[k * PX + eo];
                const float4 a1 = *(const float4*)&Xt[k * PX + eo + 4];
                const float4 bb = *(const float4*)&wdup[k * PW + cw];
                const ull b0 = pk2(bb.x, bb.y);
                const ull b1v = pk2(bb.z, bb.w);
                const ull av[4] = { pk2(a0.x, a0.y), pk2(a0.z, a0.w),
                                    pk2(a1.x, a1.y), pk2(a1.z, a1.w) };
#pragma unroll
                for (int p = 0; p < 4; p++) {
                    fma2(acc[p][0], av[p], b0);
                    fma2(acc[p][1], av[p], b1v);
                }
            }

            const int col = h * 32 + tc * 2;
            if (pass == 0) {
                const float bb0 = b1s[col], bb1 = b1s[col + 1];
#pragma unroll
                for (int p = 0; p < 4; p++) {
                    float2 v0 = up2(acc[p][0]);
                    float2 v1 = up2(acc[p][1]);
                    const int el0 = eo + 2 * p, el1 = el0 + 1;
                    float er00 = 0.f, er01 = 0.f, er10 = 0.f, er11 = 0.f;
#pragma unroll
                    for (int r = 0; r < NRBF; r++) {
                        const float w0 = erw[r * DD + col], w1 = erw[r * DD + col + 1];
                        er00 = fmaf(erbf[el0 * NRBF + r], w0, er00);
                        er01 = fmaf(erbf[el0 * NRBF + r], w1, er01);
                        er10 = fmaf(erbf[el1 * NRBF + r], w0, er10);
                        er11 = fmaf(erbf[el1 * NRBF + r], w1, er11);
                    }
                    size_t r0 = (size_t)(e0 + el0) * DD + col;
                    size_t r1 = (size_t)(e0 + el1) * DD + col;
                    *(float2*)&g_ME[r0] = make_float2(silu_f(v0.x + bb0) * er00,
                                                      silu_f(v1.x + bb1) * er01);
                    *(float2*)&g_ME[r1] = make_float2(silu_f(v0.y + bb0) * er10,
                                                      silu_f(v1.y + bb1) * er11);
                }
            } else {
                const float bb0 = b2s[col], bb1 = b2s[col + 1];
#pragma unroll
                for (int p = 0; p < 4; p++) {
                    float2 v0 = up2(acc[p][0]);
                    float2 v1 = up2(acc[p][1]);
                    const int el0 = eo + 2 * p, el1 = el0 + 1;
                    size_t r0 = (size_t)(e0 + el0) * DD + col;
                    size_t r1 = (size_t)(e0 + el1) * DD + col;
                    *(float2*)&g_TR[r0] = make_float2(silu_f(v0.x + bb0), silu_f(v1.x + bb1));
                    *(float2*)&g_TR[r1] = make_float2(silu_f(v0.y + bb0), silu_f(v1.y + bb1));
                }
            }
        }
    }
}

// ============================================================================
// K2: triplet pass -> atomic segment sum into g_S
// ============================================================================
#define K2_TW 128
__global__ __launch_bounds__(128, 8)
void k_triplet(const float* __restrict__ a_sbf, const float* __restrict__ a_sbf_w,
               const int* __restrict__ kj_idx)
{
    __shared__ float as[K2_TW * ADIM];
    __shared__ float aw[ADIM * NBIL];
    const int tid = threadIdx.x;
    const size_t w0 = (size_t)blockIdx.x * K2_TW;

    for (int i = tid; i < K2_TW * ADIM; i += 128) as[i] = a_sbf[w0 * ADIM + i];
    for (int i = tid; i < ADIM * NBIL; i += 128) aw[i] = a_sbf_w[i];
    __syncthreads();

    const float* row = &as[tid * ADIM];
    float ta[NBIL];
#pragma unroll
    for (int j = 0; j < NBIL; j++) ta[j] = 0.f;
    for (int k = 0; k < ADIM; k++) {
        const float a = row[k];
#pragma unroll
        for (int j = 0; j < NBIL; j++) ta[j] = fmaf(a, aw[k * NBIL + j], ta[j]);
    }
    const int kj = kj_idx[w0 + tid];
    float* dst = &g_S[(size_t)kj * NBIL];
#pragma unroll
    for (int j = 0; j < NBIL; j++) atomicAdd(&dst[j], ta[j]);
}

// ============================================================================
// K3: directed = (S ⊗ ME) @ final_w^T + transf -> g_X
// ============================================================================
__global__ __launch_bounds__(256, 2)
void k_einsum(const float* __restrict__ final_w)
{
    extern __shared__ float sm[];
    float* MEt  = sm;               // [128 l][PX]
    float* wdup = MEt + DD * PX;    // [128 l][PW]
    float* Ssm  = wdup + DD * PW;   // [128 e][8]

    const int tid = threadIdx.x;
    const int e0  = blockIdx.x * 128;

    for (int i = tid; i < 128 * DD; i += 256) {
        int e = i >> 7, l = i & 127;
        MEt[l * PX + e] = g_ME[(size_t)(e0 + e) * DD + l];
    }
    for (int i = tid; i < 128 * NBIL; i += 256) Ssm[i] = g_S[(size_t)e0 * NBIL + i];

    const int tc = tid & 15, te = tid >> 4;
    const int cw = tc * 4, eo = te * 8;

    for (int h = 0; h < 4; h++) {
        ull accF[4][2];
#pragma unroll
        for (int p = 0; p < 4; p++) { accF[p][0] = 0ull; accF[p][1] = 0ull; }

        for (int j = 0; j < NBIL; j++) {
            __syncthreads();
            for (int i = tid; i < 128 * 32; i += 256) {
                int ii = i >> 7, l = i & 127;
                float v = final_w[(size_t)(h * 32 + ii) * (NBIL * DD) + j * DD + l];
                wdup[l * PW + 2 * ii]     = v;
                wdup[l * PW + 2 * ii + 1] = v;
            }
            __syncthreads();

            ull acc[4][2];
#pragma unroll
            for (int p = 0; p < 4; p++) { acc[p][0] = 0ull; acc[p][1] = 0ull; }

#pragma unroll 4
            for (int l = 0; l < DD; l++) {
                const float4 a0 = *(const float4*)&MEt[l * PX + eo];
                const float4 a1 = *(const float4*)&MEt[l * PX + eo + 4];
                const float4 bb = *(const float4*)&wdup[l * PW + cw];
                const ull b0 = pk2(bb.x, bb.y);
                const ull b1v = pk2(bb.z, bb.w);
                const ull av[4] = { pk2(a0.x, a0.y), pk2(a0.z, a0.w),
                                    pk2(a1.x, a1.y), pk2(a1.z, a1.w) };
#pragma unroll
                for (int p = 0; p < 4; p++) {
                    fma2(acc[p][0], av[p], b0);
                    fma2(acc[p][1], av[p], b1v);
                }
            }

            // fold: accF += s[e,j] * acc
#pragma unroll
            for (int p = 0; p < 4; p++) {
                const int el = eo + 2 * p;
                const ull sp = pk2(Ssm[el * NBIL + j], Ssm[(el + 1) * NBIL + j]);
                fma2(accF[p][0], acc[p][0], sp);
                fma2(accF[p][1], acc[p][1], sp);
            }
        }

        // epilogue: + transf -> g_X
        const int col = h * 32 + tc * 2;
#pragma unroll
        for (int p = 0; p < 4; p++) {
            float2 v0 = up2(accF[p][0]);
            float2 v1 = up2(accF[p][1]);
            const int el = eo + 2 * p;
            size_t r0 = (size_t)(e0 + el) * DD + col;
            size_t r1 = (size_t)(e0 + el + 1) * DD + col;
            float2 t0 = *(const float2*)&g_TR[r0];
            float2 t1 = *(const float2*)&g_TR[r1];
            *(float2*)&g_X[r0] = make_float2(v0.x + t0.x, v1.x + t0.y);
            *(float2*)&g_X[r1] = make_float2(v0.y + t1.x, v1.y + t1.y);
        }
    }
}

// ============================================================================
// K4: dense row layer: Y = silu(X@W + b) [+ skip]
// ============================================================================
__global__ __launch_bounds__(256, 2)
void k_layer(const float* __restrict__ X, const float* __restrict__ W,
             const float* __restrict__ b, const float* __restrict__ skip,
             float* __restrict__ Y)
{
    extern __shared__ float sm[];
    float* Xt   = sm;              // [128 k][PX]
    float* wdup = Xt + DD * PX;    // [128 k][PW]
    float* bias = wdup + DD * PW;  // [128]

    const int tid = threadIdx.x;
    const int e0  = blockIdx.x * 128;

    for (int i = tid; i < 128 * DD; i += 256) {
        int e = i >> 7, d = i & 127;
        Xt[d * PX + e] = X[(size_t)(e0 + e) * DD + d];
    }
    if (tid < DD) bias[tid] = b[tid];

    const int tc = tid & 15, te = tid >> 4;
    const int cw = tc * 4, eo = te * 8;

    for (int h = 0; h < 4; h++) {
        __syncthreads();
        for (int i = tid; i < 128 * 32; i += 256) {
            int k = i >> 5, c = i & 31;
            float v = W[k * DD + h * 32 + c];
            wdup[k * PW + 2 * c]     = v;
            wdup[k * PW + 2 * c + 1] = v;
        }
        __syncthreads();

        ull acc[4][2];
#pragma unroll
        for (int p = 0; p < 4; p++) { acc[p][0] = 0ull; acc[p][1] = 0ull; }

#pragma unroll 4
        for (int k = 0; k < DD; k++) {
            const float4 a0 = *(const float4*)&Xt[k * PX + eo];
            const float4 a1 = *(const float4*)&Xt[k * PX + eo + 4];
            const float4 bb = *(const float4*)&wdup[k * PW + cw];
            const ull b0 = pk2(bb.x, bb.y);
            const ull b1v = pk2(bb.z, bb.w);
            const ull av[4] = { pk2(a0.x, a0.y), pk2(a0.z, a0.w),
                                pk2(a1.x, a1.y), pk2(a1.z, a1.w) };
#pragma unroll
            for (int p = 0; p < 4; p++) {
                fma2(acc[p][0], av[p], b0);
                fma2(acc[p][1], av[p], b1v);
            }
        }

        const int col = h * 32 + tc * 2;
        const float bb0 = bias[col], bb1 = bias[col + 1];
#pragma unroll
        for (int p = 0; p < 4; p++) {
            float2 v0 = up2(acc[p][0]);
            float2 v1 = up2(acc[p][1]);
            const int el = eo + 2 * p;
            size_t r0 = (size_t)(e0 + el) * DD + col;
            size_t r1 = (size_t)(e0 + el + 1) * DD + col;
            float o00 = silu_f(v0.x + bb0), o01 = silu_f(v1.x + bb1);
            float o10 = silu_f(v0.y + bb0), o11 = silu_f(v1.y + bb1);
            if (skip) {
                float2 s0 = *(const float2*)&skip[r0];
                float2 s1 = *(const float2*)&skip[r1];
                o00 += s0.x; o01 += s0.y; o10 += s1.x; o11 += s1.y;
            }
            *(float2*)&Y[r0] = make_float2(o00, o01);
            *(float2*)&Y[r1] = make_float2(o10, o11);
        }
    }
}

// ============================================================================
// host launcher
// ============================================================================
extern "C" void kernel_launch(void* const* d_in, const int* in_sizes, int n_in,
                              void* d_out, int out_size)
{
    const float* m_ji    = (const float*)d_in[0];
    const float* e_rbf   = (const float*)d_in[1];
    const float* a_sbf   = (const float*)d_in[2];
    const int*   kj_idx  = (const int*)d_in[5];
    const float* nbr_m_w = (const float*)d_in[6];
    const float* nbr_m_b = (const float*)d_in[7];
    const float* e_rbf_w = (const float*)d_in[8];
    const float* a_sbf_w = (const float*)d_in[9];
    const float* final_w = (const float*)d_in[10];
    const float* m_ji_w  = (const float*)d_in[11];
    const float* m_ji_b  = (const float*)d_in[12];
    const float* post_w  = (const float*)d_in[13];
    const float* post_b  = (const float*)d_in[14];
    const float* res_w   = (const float*)d_in[15];
    const float* res_b   = (const float*)d_in[16];
    float* out = (float*)d_out;

    float *pX, *pH, *pTR;
    cudaGetSymbolAddress((void**)&pX,  g_X);
    cudaGetSymbolAddress((void**)&pH,  g_H);
    cudaGetSymbolAddress((void**)&pTR, g_TR);

    const int SMEM1 = (DD * PX + DD * PW + DD * NRBF + NRBF * DD + 2 * DD) * 4;
    const int SMEM3 = (DD * PX + DD * PW + 128 * NBIL) * 4;
    const int SMEM4 = (DD * PX + DD * PW + DD) * 4;
    cudaFuncSetAttribute(k_edge_pre, cudaFuncAttributeMaxDynamicSharedMemorySize, SMEM1);
    cudaFuncSetAttribute(k_einsum,   cudaFuncAttributeMaxDynamicSharedMemorySize, SMEM3);
    cudaFuncSetAttribute(k_layer,    cudaFuncAttributeMaxDynamicSharedMemorySize, SMEM4);

    k_edge_pre<<<NE / 128, 256, SMEM1>>>(m_ji, e_rbf, nbr_m_w, nbr_m_b,
                                         e_rbf_w, m_ji_w, m_ji_b);
    k_triplet<<<NW / K2_TW, 128>>>(a_sbf, a_sbf_w, kj_idx);
    k_einsum<<<NE / 128, 256, SMEM3>>>(final_w);

    const int WD = DD * DD;
    k_layer<<<NE / 128, 256, SMEM4>>>(pX, res_w + 0 * WD, res_b + 0 * DD, nullptr, pH);
    k_layer<<<NE / 128, 256, SMEM4>>>(pH, res_w + 1 * WD, res_b + 1 * DD, pX, pX);
    k_layer<<<NE / 128, 256, SMEM4>>>(pX, post_w, post_b, pTR, pX);
    k_layer<<<NE / 128, 256, SMEM4>>>(pX, res_w + 2 * WD, res_b + 2 * DD, nullptr, pH);
    k_layer<<<NE / 128, 256, SMEM4>>>(pH, res_w + 3 * WD, res_b + 3 * DD, pX, pX);
    k_layer<<<NE / 128, 256, SMEM4>>>(pX, res_w + 4 * WD, res_b + 4 * DD, nullptr, pH);
    k_layer<<<NE / 128, 256, SMEM4>>>(pH, res_w + 5 * WD, res_b + 5 * DD, pX, out);
}